// round 5
// baseline (speedup 1.0000x reference)
#include <cuda_runtime.h>
#include <cuda_fp16.h>

// Problem constants (fixed shapes)
#define NU 100000
#define NI 50000
#define NN 150000        // NU + NI
#define D  64
#define DE 16
#define NE 1500000
#define NP 14
#define EPS 1e-5f

#define NN2 (2 * NN)     // 300000 (both layers' row counters)
#define NE2 (2 * NE)     // 3000000 (both layers' CSR)
#define SCAN_BLK 1024
#define NB2 ((NN2 + SCAN_BLK - 1) / SCAN_BLK)  // 293
#define ROWB ((NN + 7) / 8)                     // 18750 (8 warps/block)
#define HISTB ((NE2 / 4 + 255) / 256)           // 2930

// -------- scratch (device globals; no allocation allowed) --------
__device__ __half g_yh0[NN * D];    // LN features layer 0 (fp16)
__device__ __half g_yh1[NN * D];    // LN features layer 1 (fp16)
__device__ __half g_eh [NN * DE];   // eigs fp16 (built once per run)
__device__ float  g_x0 [NN * D];    // layer-0 output (fp32, needed for final avg)
__device__ int    g_cnt[NN2];       // row degrees, both layers contiguous
__device__ int    g_rs [NN2];       // CSR row starts (global over 2*NE)
__device__ int    g_cur[NN2];       // scatter cursors
__device__ int2   g_csr[NE2 + 8];   // (col, e1-as-float-bits), both layers
__device__ int    g_part[512];      // scan partials
__device__ int    g_scan_ctr;       // scan completion counter

// ---------------------------------------------------------------
// K0: zero counters, reset scan counter, convert eigs -> fp16.
// ---------------------------------------------------------------
__global__ void prep_kernel(const float* __restrict__ eigs)
{
    int i = blockIdx.x * blockDim.x + threadIdx.x;
    if (i == 0) g_scan_ctr = 0;
    if (i < NN2 / 4) ((int4*)g_cnt)[i] = make_int4(0, 0, 0, 0);
    if (i < NN * DE / 2) {
        float2 v = ((const float2*)eigs)[i];
        ((__half2*)g_eh)[i] = __floats2half2_rn(v.x, v.y);
    }
}

// ---------------------------------------------------------------
// K1: fused LN(layer 0) + histogram(both layers).
//   blocks [0, ROWB)          : warp-per-row LN of concat(ue,ie) -> yh0
//   blocks [ROWB, ROWB+HISTB) : histogram of rows into g_cnt (both layers)
// (g_cnt pre-zeroed in K0 — no in-kernel zeroing; R3's race.)
// ---------------------------------------------------------------
__global__ void ln_hist_kernel(const float* __restrict__ ue,
                               const float* __restrict__ ie,
                               const int*   __restrict__ idx)
{
    if (blockIdx.x < ROWB) {
        int row = blockIdx.x * 8 + (threadIdx.x >> 5);
        if (row >= NN) return;
        int lane = threadIdx.x & 31;

        const float* p = (row < NU) ? (ue + (size_t)row * D)
                                    : (ie + (size_t)(row - NU) * D);
        float2 v = ((const float2*)p)[lane];

        float s = v.x + v.y;
        #pragma unroll
        for (int o = 16; o; o >>= 1) s += __shfl_xor_sync(0xffffffffu, s, o);
        float mu = s * (1.0f / D);

        float dx = v.x - mu, dy = v.y - mu;
        float vs = dx * dx + dy * dy;
        #pragma unroll
        for (int o = 16; o; o >>= 1) vs += __shfl_xor_sync(0xffffffffu, vs, o);
        float inv = rsqrtf(vs * (1.0f / D) + EPS);

        ((__half2*)(g_yh0 + (size_t)row * D))[lane] =
            __floats2half2_rn(dx * inv, dy * inv);
    } else {
        int e4 = (blockIdx.x - ROWB) * blockDim.x + threadIdx.x;
        if (e4 < NE2 / 4) {
            int layer = (e4 >= NE / 4);
            const int* rows = idx + (size_t)layer * 2 * NE;
            int4 r4 = ((const int4*)rows)[e4 - layer * (NE / 4)];
            int base = layer * NN;
            atomicAdd(&g_cnt[base + r4.x], 1);
            atomicAdd(&g_cnt[base + r4.y], 1);
            atomicAdd(&g_cnt[base + r4.z], 1);
            atomicAdd(&g_cnt[base + r4.w], 1);
        }
    }
}

// ---------------------------------------------------------------
// K2/K3: exclusive scan of g_cnt[NN2] -> g_rs, g_cur.
// ---------------------------------------------------------------
__device__ __forceinline__ int warp_incl_scan(int x, int lane)
{
    #pragma unroll
    for (int o = 1; o < 32; o <<= 1) {
        int t = __shfl_up_sync(0xffffffffu, x, o);
        if (lane >= o) x += t;
    }
    return x;
}

__global__ void scan_kernel()
{
    __shared__ int warpsum[32];
    __shared__ int s_total;
    __shared__ int s_isLast;

    int lane = threadIdx.x & 31;
    int wid  = threadIdx.x >> 5;
    int i = blockIdx.x * SCAN_BLK + threadIdx.x;
    int v = (i < NN2) ? g_cnt[i] : 0;

    int inc = warp_incl_scan(v, lane);
    if (lane == 31) warpsum[wid] = inc;
    __syncthreads();
    if (wid == 0) {
        int s  = warpsum[lane];
        int si = warp_incl_scan(s, lane);
        warpsum[lane] = si - s;
        if (lane == 31) s_total = si;
    }
    __syncthreads();
    int excl = inc - v + warpsum[wid];
    if (i < NN2) g_rs[i] = excl;

    if (threadIdx.x == 0) {
        g_part[blockIdx.x] = s_total;
        __threadfence();
        s_isLast = (atomicAdd(&g_scan_ctr, 1) == (int)gridDim.x - 1);
    }
    __syncthreads();

    if (s_isLast) {
        int pv = (threadIdx.x < NB2) ? g_part[threadIdx.x] : 0;
        int inc2 = warp_incl_scan(pv, lane);
        __syncthreads();
        if (lane == 31) warpsum[wid] = inc2;
        __syncthreads();
        if (wid == 0) {
            int s  = warpsum[lane];
            int si = warp_incl_scan(s, lane);
            warpsum[lane] = si - s;
        }
        __syncthreads();
        int excl2 = inc2 - pv + warpsum[wid];
        if (threadIdx.x < NB2) g_part[threadIdx.x] = excl2;
    }
}

__global__ void scan3_kernel()
{
    int i = blockIdx.x * blockDim.x + threadIdx.x;
    if (i >= NN2) return;
    int v = g_rs[i] + g_part[i >> 10];
    g_rs[i]  = v;
    g_cur[i] = v;
}

// ---------------------------------------------------------------
// K4: scatter both layers' edges into CSR order.
//   csr[pos] = (col, min(exp(pw[pt]), 5) as bits)
// ---------------------------------------------------------------
__global__ void scatter_kernel(const int*   __restrict__ idx,
                               const int*   __restrict__ pt,
                               const float* __restrict__ pw)
{
    int e = blockIdx.x * blockDim.x + threadIdx.x;
    if (e >= NE2) return;
    int layer = (e >= NE);
    int le = e - layer * NE;
    const int* rows = idx + (size_t)layer * 2 * NE;
    int r = __ldg(rows + le);
    int c = __ldg(rows + NE + le);
    int ptv = __ldg(pt + (size_t)layer * NE + le);
    float w = fminf(__expf(__ldg(pw + layer * NP + ptv)), 5.0f);
    int pos = atomicAdd(&g_cur[layer * NN + r], 1);
    g_csr[pos] = make_int2(c, __float_as_int(w));
}

// ---------------------------------------------------------------
// Fused per-row aggregate: warp per row, 4 edges/iteration.
// Lane layout: group g = lane>>3 handles edge (i+g); pos q = lane&7
// covers feature dims [8q, 8q+8). Score butterfly within groups
// (xor 1,2,4); per-row accumulators cross-group reduced at the end.
// ---------------------------------------------------------------
__device__ __forceinline__ void unpack8(uint4 u, float* f)
{
    float2 t;
    t = __half22float2(*(__half2*)&u.x); f[0] = t.x; f[1] = t.y;
    t = __half22float2(*(__half2*)&u.y); f[2] = t.x; f[3] = t.y;
    t = __half22float2(*(__half2*)&u.z); f[4] = t.x; f[5] = t.y;
    t = __half22float2(*(__half2*)&u.w); f[6] = t.x; f[7] = t.y;
}

__device__ __forceinline__ void row_aggregate(
    int row, int base, const __half* __restrict__ yh,
    float elam, int g, int q, float* out8)
{
    int n  = g_cnt[base + row];
    int st = g_rs[base + row];

    uint4 au = __ldg((const uint4*)(yh + (size_t)row * D) + q);
    float ar[8]; unpack8(au, ar);
    __half2 eu = __ldg((const __half2*)(g_eh + (size_t)row * DE) + q);
    float2 er = __half22float2(eu);

    float s0 = 0.f, s1 = 0.f;
    float ax0[8], ax1[8];
    #pragma unroll
    for (int k = 0; k < 8; k++) { ax0[k] = 0.f; ax1[k] = 0.f; }

    for (int i = 0; i < n; i += 4) {
        int j = i + g;
        bool valid = (j < n);
        int slot = st + (valid ? j : 0);
        int2 cw = __ldg(&g_csr[slot]);
        int c = cw.x;
        float e1 = valid ? __int_as_float(cw.y) : 0.f;

        uint4 bu = __ldg((const uint4*)(yh + (size_t)c * D) + q);
        float br[8]; unpack8(bu, br);

        float part = ar[0]*br[0] + ar[1]*br[1] + ar[2]*br[2] + ar[3]*br[3]
                   + ar[4]*br[4] + ar[5]*br[5] + ar[6]*br[6] + ar[7]*br[7];
        part *= 0.125f;                                   // 1/sqrt(64)
        __half2 ech = __ldg((const __half2*)(g_eh + (size_t)c * DE) + q);
        float2 ec = __half22float2(ech);
        part += elam * (er.x * ec.x + er.y * ec.y);

        part += __shfl_xor_sync(0xffffffffu, part, 1);
        part += __shfl_xor_sync(0xffffffffu, part, 2);
        part += __shfl_xor_sync(0xffffffffu, part, 4);

        float e0 = valid ? fminf(__expf(part), 5.0f) : 0.f;
        s0 += e0; s1 += e1;
        #pragma unroll
        for (int k = 0; k < 8; k++) { ax0[k] += e0 * br[k]; ax1[k] += e1 * br[k]; }
    }

    // cross-group reduce (groups differ in lane bits 3,4)
    s0 += __shfl_xor_sync(0xffffffffu, s0, 8);
    s0 += __shfl_xor_sync(0xffffffffu, s0, 16);
    s1 += __shfl_xor_sync(0xffffffffu, s1, 8);
    s1 += __shfl_xor_sync(0xffffffffu, s1, 16);
    #pragma unroll
    for (int k = 0; k < 8; k++) {
        ax0[k] += __shfl_xor_sync(0xffffffffu, ax0[k], 8);
        ax0[k] += __shfl_xor_sync(0xffffffffu, ax0[k], 16);
        ax1[k] += __shfl_xor_sync(0xffffffffu, ax1[k], 8);
        ax1[k] += __shfl_xor_sync(0xffffffffu, ax1[k], 16);
    }

    float i0 = 0.5f / ((s0 == 0.f) ? 1.f : s0);
    float i1 = 0.5f / ((s1 == 0.f) ? 1.f : s1);
    #pragma unroll
    for (int k = 0; k < 8; k++) out8[k] = ax0[k] * i0 + ax1[k] * i1;
}

// ---------------------------------------------------------------
// K5: layer 0 — aggregate -> x0 (fp32) and in-register LN -> yh1.
// ---------------------------------------------------------------
__global__ void fused0_kernel(const float* __restrict__ lam)
{
    int row = blockIdx.x * 8 + (threadIdx.x >> 5);
    if (row >= NN) return;
    int lane = threadIdx.x & 31, g = lane >> 3, q = lane & 7;
    float elam = __expf(__ldg(lam));

    float o[8];
    row_aggregate(row, 0, g_yh0, elam, g, q, o);

    // LayerNorm over the 64-dim row (lanes with the same q hold copies;
    // butterfly over q within each group gives the full-row sums)
    float s = o[0]+o[1]+o[2]+o[3]+o[4]+o[5]+o[6]+o[7];
    s += __shfl_xor_sync(0xffffffffu, s, 1);
    s += __shfl_xor_sync(0xffffffffu, s, 2);
    s += __shfl_xor_sync(0xffffffffu, s, 4);
    float mu = s * (1.0f / D);
    float dx[8], vs = 0.f;
    #pragma unroll
    for (int k = 0; k < 8; k++) { dx[k] = o[k] - mu; vs += dx[k] * dx[k]; }
    vs += __shfl_xor_sync(0xffffffffu, vs, 1);
    vs += __shfl_xor_sync(0xffffffffu, vs, 2);
    vs += __shfl_xor_sync(0xffffffffu, vs, 4);
    float inv = rsqrtf(vs * (1.0f / D) + EPS);

    if (lane < 8) {
        float4* xp = (float4*)(g_x0 + (size_t)row * D + 8 * q);
        xp[0] = make_float4(o[0], o[1], o[2], o[3]);
        xp[1] = make_float4(o[4], o[5], o[6], o[7]);
        __half2 h[4];
        #pragma unroll
        for (int k = 0; k < 4; k++)
            h[k] = __floats2half2_rn(dx[2*k] * inv, dx[2*k+1] * inv);
        *(uint4*)(g_yh1 + (size_t)row * D + 8 * q) = *(uint4*)h;
    }
}

// ---------------------------------------------------------------
// K6: layer 1 — aggregate -> x1 (in regs); out = (emb + x0 + x1)/3.
// ---------------------------------------------------------------
__global__ void fused1_kernel(const float* __restrict__ ue,
                              const float* __restrict__ ie,
                              const float* __restrict__ lam,
                              float* __restrict__ out)
{
    int row = blockIdx.x * 8 + (threadIdx.x >> 5);
    if (row >= NN) return;
    int lane = threadIdx.x & 31, g = lane >> 3, q = lane & 7;
    float elam = __expf(__ldg(lam));

    float o[8];
    row_aggregate(row, NN, g_yh1, elam, g, q, o);

    if (lane < 8) {
        const float* emb = (row < NU) ? (ue + (size_t)row * D)
                                      : (ie + (size_t)(row - NU) * D);
        float4 ea = *(const float4*)(emb + 8 * q);
        float4 eb = *(const float4*)(emb + 8 * q + 4);
        float4 xa = *(const float4*)(g_x0 + (size_t)row * D + 8 * q);
        float4 xb = *(const float4*)(g_x0 + (size_t)row * D + 8 * q + 4);
        const float t = 1.0f / 3.0f;
        float4 oa = make_float4((ea.x + xa.x + o[0]) * t, (ea.y + xa.y + o[1]) * t,
                                (ea.z + xa.z + o[2]) * t, (ea.w + xa.w + o[3]) * t);
        float4 ob = make_float4((eb.x + xb.x + o[4]) * t, (eb.y + xb.y + o[5]) * t,
                                (eb.z + xb.z + o[6]) * t, (eb.w + xb.w + o[7]) * t);
        float4* op = (float4*)(out + (size_t)row * D + 8 * q);
        op[0] = oa;
        op[1] = ob;
    }
}

extern "C" void kernel_launch(void* const* d_in, const int* in_sizes, int n_in,
                              void* d_out, int out_size)
{
    const float* ue   = (const float*)d_in[0];  // [NU, D]
    const float* ie   = (const float*)d_in[1];  // [NI, D]
    const float* eigs = (const float*)d_in[2];  // [NN, DE]
    const float* lam  = (const float*)d_in[3];  // [2]
    const float* pw   = (const float*)d_in[4];  // [2, NP]
    const int*   idx  = (const int*)  d_in[5];  // [2, 2, NE]
    const int*   pt   = (const int*)  d_in[6];  // [2, NE]
    float* out = (float*)d_out;

    prep_kernel   <<<(NN * DE / 2 + 255) / 256, 256>>>(eigs);
    ln_hist_kernel<<<ROWB + HISTB, 256>>>(ue, ie, idx);
    scan_kernel   <<<NB2, SCAN_BLK>>>();
    scan3_kernel  <<<(NN2 + 255) / 256, 256>>>();
    scatter_kernel<<<(NE2 + 255) / 256, 256>>>(idx, pt, pw);
    fused0_kernel <<<ROWB, 256>>>(lam);
    fused1_kernel <<<ROWB, 256>>>(ue, ie, lam + 1, out);
}

// round 6
// speedup vs baseline: 1.0428x; 1.0428x over previous
#include <cuda_runtime.h>
#include <cuda_fp16.h>

// Problem constants (fixed shapes)
#define NU 100000
#define NI 50000
#define NN 150000        // NU + NI
#define D  64
#define DE 16
#define NE 1500000
#define NP 14
#define EPS 1e-5f

#define NN2 (2 * NN)     // row counters for both layers
#define NE2 (2 * NE)     // CSR slots for both layers
#define SCAN_BLK 1024
#define NB2 ((NN2 + SCAN_BLK - 1) / SCAN_BLK)  // 293
#define ROWB ((NN + 7) / 8)                     // 18750 (8 warps/block)
#define HISTB ((NE2 / 4 + 255) / 256)           // 2930

// -------- scratch (device globals; no allocation allowed) --------
__device__ __half g_yh0[NN * D];    // LN features layer 0 (fp16)
__device__ __half g_yh1[NN * D];    // LN features layer 1 (fp16)
__device__ __half g_eh [NN * DE];   // eigs fp16
__device__ float  g_x0 [NN * D];    // layer-0 output (fp32 for final avg)
__device__ int    g_cnt[NN2];       // row degrees (both layers)
__device__ int    g_rs [NN2];       // CSR row starts (global over NE2)
__device__ int    g_cur[NN2];       // scatter cursors
__device__ int    g_csr_r[NE2];     // CSR: row index per slot
__device__ int2   g_csr  [NE2];     // CSR: (col, e1 bits)
__device__ float  g_e0 [NE2];       // per-slot exp attention score
__device__ float  g_s0 [NN2];       // softmax-0 row sums
__device__ float  g_s1 [NN2];       // softmax-1 row sums
__device__ int    g_part[512];      // scan partials
__device__ int    g_scan_ctr;

// ---------------------------------------------------------------
// K0: zero counters/sums, reset scan counter, eigs -> fp16.
// ---------------------------------------------------------------
__global__ void prep_kernel(const float* __restrict__ eigs)
{
    int i = blockIdx.x * blockDim.x + threadIdx.x;
    if (i == 0) g_scan_ctr = 0;
    if (i < NN2) { g_cnt[i] = 0; g_s0[i] = 0.f; g_s1[i] = 0.f; }
    if (i < NN * DE / 2) {
        float2 v = ((const float2*)eigs)[i];
        ((__half2*)g_eh)[i] = __floats2half2_rn(v.x, v.y);
    }
}

// ---------------------------------------------------------------
// K1: fused LN(layer 0) + histogram(both layers).
// g_cnt pre-zeroed in K0 (no in-kernel zeroing — R3's race).
// ---------------------------------------------------------------
__global__ void ln_hist_kernel(const float* __restrict__ ue,
                               const float* __restrict__ ie,
                               const int*   __restrict__ idx)
{
    if (blockIdx.x < ROWB) {
        int row = blockIdx.x * 8 + (threadIdx.x >> 5);
        if (row >= NN) return;
        int lane = threadIdx.x & 31;

        const float* p = (row < NU) ? (ue + (size_t)row * D)
                                    : (ie + (size_t)(row - NU) * D);
        float2 v = ((const float2*)p)[lane];

        float s = v.x + v.y;
        #pragma unroll
        for (int o = 16; o; o >>= 1) s += __shfl_xor_sync(0xffffffffu, s, o);
        float mu = s * (1.0f / D);

        float dx = v.x - mu, dy = v.y - mu;
        float vs = dx * dx + dy * dy;
        #pragma unroll
        for (int o = 16; o; o >>= 1) vs += __shfl_xor_sync(0xffffffffu, vs, o);
        float inv = rsqrtf(vs * (1.0f / D) + EPS);

        ((__half2*)(g_yh0 + (size_t)row * D))[lane] =
            __floats2half2_rn(dx * inv, dy * inv);
    } else {
        int e4 = (blockIdx.x - ROWB) * blockDim.x + threadIdx.x;
        if (e4 < NE2 / 4) {
            int layer = (e4 >= NE / 4);
            const int* rows = idx + (size_t)layer * 2 * NE;
            int4 r4 = ((const int4*)rows)[e4 - layer * (NE / 4)];
            int base = layer * NN;
            atomicAdd(&g_cnt[base + r4.x], 1);
            atomicAdd(&g_cnt[base + r4.y], 1);
            atomicAdd(&g_cnt[base + r4.z], 1);
            atomicAdd(&g_cnt[base + r4.w], 1);
        }
    }
}

// ---------------------------------------------------------------
// K2/K3: exclusive scan of g_cnt[NN2] -> g_rs, g_cur.
// ---------------------------------------------------------------
__device__ __forceinline__ int warp_incl_scan(int x, int lane)
{
    #pragma unroll
    for (int o = 1; o < 32; o <<= 1) {
        int t = __shfl_up_sync(0xffffffffu, x, o);
        if (lane >= o) x += t;
    }
    return x;
}

__global__ void scan_kernel()
{
    __shared__ int warpsum[32];
    __shared__ int s_total;
    __shared__ int s_isLast;

    int lane = threadIdx.x & 31;
    int wid  = threadIdx.x >> 5;
    int i = blockIdx.x * SCAN_BLK + threadIdx.x;
    int v = (i < NN2) ? g_cnt[i] : 0;

    int inc = warp_incl_scan(v, lane);
    if (lane == 31) warpsum[wid] = inc;
    __syncthreads();
    if (wid == 0) {
        int s  = warpsum[lane];
        int si = warp_incl_scan(s, lane);
        warpsum[lane] = si - s;
        if (lane == 31) s_total = si;
    }
    __syncthreads();
    int excl = inc - v + warpsum[wid];
    if (i < NN2) g_rs[i] = excl;

    if (threadIdx.x == 0) {
        g_part[blockIdx.x] = s_total;
        __threadfence();
        s_isLast = (atomicAdd(&g_scan_ctr, 1) == (int)gridDim.x - 1);
    }
    __syncthreads();

    if (s_isLast) {
        int pv = (threadIdx.x < NB2) ? g_part[threadIdx.x] : 0;
        int inc2 = warp_incl_scan(pv, lane);
        __syncthreads();
        if (lane == 31) warpsum[wid] = inc2;
        __syncthreads();
        if (wid == 0) {
            int s  = warpsum[lane];
            int si = warp_incl_scan(s, lane);
            warpsum[lane] = si - s;
        }
        __syncthreads();
        int excl2 = inc2 - pv + warpsum[wid];
        if (threadIdx.x < NB2) g_part[threadIdx.x] = excl2;
    }
}

__global__ void scan3_kernel()
{
    int i = blockIdx.x * blockDim.x + threadIdx.x;
    if (i >= NN2) return;
    int v = g_rs[i] + g_part[i >> 10];
    g_rs[i]  = v;
    g_cur[i] = v;
}

// ---------------------------------------------------------------
// K4: scatter both layers' edges into CSR order.
// ---------------------------------------------------------------
__global__ void scatter_kernel(const int*   __restrict__ idx,
                               const int*   __restrict__ pt,
                               const float* __restrict__ pw)
{
    int e = blockIdx.x * blockDim.x + threadIdx.x;
    if (e >= NE2) return;
    int layer = (e >= NE);
    int le = e - layer * NE;
    const int* rows = idx + (size_t)layer * 2 * NE;
    int r = __ldg(rows + le);
    int c = __ldg(rows + NE + le);
    int ptv = __ldg(pt + (size_t)layer * NE + le);
    float w = fminf(__expf(__ldg(pw + layer * NP + ptv)), 5.0f);
    int pos = atomicAdd(&g_cur[layer * NN + r], 1);
    g_csr_r[pos] = r;
    g_csr[pos]   = make_int2(c, __float_as_int(w));
}

// ---------------------------------------------------------------
// K5: scores over CSR slots (4 lanes/slot). Consecutive slots share
// r -> yh[r]/eigs[r] loads hit L1. Writes e0[slot], atomics s0/s1.
// ---------------------------------------------------------------
__device__ __forceinline__ float dot8h(uint4 a, uint4 b)
{
    const __half2* ah = (const __half2*)&a;
    const __half2* bh = (const __half2*)&b;
    float d = 0.f;
    #pragma unroll
    for (int j = 0; j < 4; j++) {
        float2 af = __half22float2(ah[j]);
        float2 bf = __half22float2(bh[j]);
        d += af.x * bf.x + af.y * bf.y;
    }
    return d;
}

__global__ void score_kernel(const __half* __restrict__ yh,
                             int slotBase, int rowBase,
                             const float* __restrict__ lam)
{
    int t = blockIdx.x * blockDim.x + threadIdx.x;
    int sl = t >> 2;
    if (sl >= NE) return;
    int slot = slotBase + sl;
    int q = t & 3;

    int r = __ldg(&g_csr_r[slot]);
    int2 cw = __ldg(&g_csr[slot]);
    int c = cw.x;

    const uint4* ar = (const uint4*)(yh + (size_t)r * D);
    const uint4* bc = (const uint4*)(yh + (size_t)c * D);
    float dp = dot8h(__ldg(ar + q), __ldg(bc + q))
             + dot8h(__ldg(ar + q + 4), __ldg(bc + q + 4));

    // eigs: 16 halves per node; each lane covers 4 dims (uint2 = 2 half2)
    uint2 eu = __ldg((const uint2*)(g_eh + (size_t)r * DE) + q);
    uint2 ev = __ldg((const uint2*)(g_eh + (size_t)c * DE) + q);
    float2 e0f = __half22float2(*(__half2*)&eu.x);
    float2 e1f = __half22float2(*(__half2*)&eu.y);
    float2 f0f = __half22float2(*(__half2*)&ev.x);
    float2 f1f = __half22float2(*(__half2*)&ev.y);
    float ys = e0f.x * f0f.x + e0f.y * f0f.y + e1f.x * f1f.x + e1f.y * f1f.y;

    float elam = __expf(__ldg(lam));
    float p = dp * 0.125f + elam * ys;
    p += __shfl_xor_sync(0xffffffffu, p, 1);
    p += __shfl_xor_sync(0xffffffffu, p, 2);

    if (q == 0) {
        float v0 = fminf(__expf(p), 5.0f);
        g_e0[slot] = v0;
        atomicAdd(&g_s0[rowBase + r], v0);
    } else if (q == 1) {
        atomicAdd(&g_s1[rowBase + r], __int_as_float(cw.y));
    }
}

// ---------------------------------------------------------------
// K6: SpMM (warp/row, lane = 2 dims, 2-wide unroll for MLP) with
// fused epilogue. MODE 0: LN -> yh1 fp16 + x0 fp32.
//                 MODE 1: out = (emb + x0 + x)/3.
// ---------------------------------------------------------------
template<int MODE>
__global__ void spmm_kernel(const __half* __restrict__ yh,
                            int rowBase,
                            const float* __restrict__ ue,
                            const float* __restrict__ ie,
                            float* __restrict__ out)
{
    int row = blockIdx.x * 8 + (threadIdx.x >> 5);
    if (row >= NN) return;
    int lane = threadIdx.x & 31;

    int n  = g_cnt[rowBase + row];
    int st = g_rs [rowBase + row];
    float d0 = g_s0[rowBase + row]; d0 = (d0 == 0.f) ? 1.f : d0;
    float d1 = g_s1[rowBase + row]; d1 = (d1 == 0.f) ? 1.f : d1;
    float i0 = 0.5f / d0, i1 = 0.5f / d1;

    float ax = 0.f, ay = 0.f;
    int i = 0;
    for (; i + 2 <= n; i += 2) {
        int2  cwA = __ldg(&g_csr[st + i]);
        int2  cwB = __ldg(&g_csr[st + i + 1]);
        float eA  = __ldg(&g_e0[st + i]);
        float eB  = __ldg(&g_e0[st + i + 1]);
        __half2 hA = ((const __half2*)(yh + (size_t)cwA.x * D))[lane];
        __half2 hB = ((const __half2*)(yh + (size_t)cwB.x * D))[lane];
        float sA = eA * i0 + __int_as_float(cwA.y) * i1;
        float sB = eB * i0 + __int_as_float(cwB.y) * i1;
        float2 vA = __half22float2(hA);
        float2 vB = __half22float2(hB);
        ax += sA * vA.x + sB * vB.x;
        ay += sA * vA.y + sB * vB.y;
    }
    if (i < n) {
        int2  cw = __ldg(&g_csr[st + i]);
        float e  = __ldg(&g_e0[st + i]);
        __half2 h = ((const __half2*)(yh + (size_t)cw.x * D))[lane];
        float s = e * i0 + __int_as_float(cw.y) * i1;
        float2 v = __half22float2(h);
        ax += s * v.x;
        ay += s * v.y;
    }

    if (MODE == 0) {
        // fused LayerNorm -> yh1 (fp16), plus x0 (fp32)
        float s = ax + ay;
        #pragma unroll
        for (int o = 16; o; o >>= 1) s += __shfl_xor_sync(0xffffffffu, s, o);
        float mu = s * (1.0f / D);
        float dx = ax - mu, dy = ay - mu;
        float vs = dx * dx + dy * dy;
        #pragma unroll
        for (int o = 16; o; o >>= 1) vs += __shfl_xor_sync(0xffffffffu, vs, o);
        float inv = rsqrtf(vs * (1.0f / D) + EPS);

        ((float2*)(g_x0 + (size_t)row * D))[lane] = make_float2(ax, ay);
        ((__half2*)(g_yh1 + (size_t)row * D))[lane] =
            __floats2half2_rn(dx * inv, dy * inv);
    } else {
        const float* emb = (row < NU) ? (ue + (size_t)row * D)
                                      : (ie + (size_t)(row - NU) * D);
        float2 e = ((const float2*)emb)[lane];
        float2 x = ((const float2*)(g_x0 + (size_t)row * D))[lane];
        const float t = 1.0f / 3.0f;
        ((float2*)(out + (size_t)row * D))[lane] =
            make_float2((e.x + x.x + ax) * t, (e.y + x.y + ay) * t);
    }
}

extern "C" void kernel_launch(void* const* d_in, const int* in_sizes, int n_in,
                              void* d_out, int out_size)
{
    const float* ue   = (const float*)d_in[0];  // [NU, D]
    const float* ie   = (const float*)d_in[1];  // [NI, D]
    const float* eigs = (const float*)d_in[2];  // [NN, DE]
    const float* lam  = (const float*)d_in[3];  // [2]
    const float* pw   = (const float*)d_in[4];  // [2, NP]
    const int*   idx  = (const int*)  d_in[5];  // [2, 2, NE]
    const int*   pt   = (const int*)  d_in[6];  // [2, NE]
    float* out = (float*)d_out;

    __half* yh0 = nullptr; __half* yh1 = nullptr;
    cudaGetSymbolAddress((void**)&yh0, g_yh0);
    cudaGetSymbolAddress((void**)&yh1, g_yh1);

    int prepT = NN * DE / 2;                     // 1.2M (covers NN2 too)
    prep_kernel   <<<(prepT + 255) / 256, 256>>>(eigs);
    ln_hist_kernel<<<ROWB + HISTB, 256>>>(ue, ie, idx);
    scan_kernel   <<<NB2, SCAN_BLK>>>();
    scan3_kernel  <<<(NN2 + 255) / 256, 256>>>();
    scatter_kernel<<<(NE2 + 255) / 256, 256>>>(idx, pt, pw);

    int scoreB = (NE * 4 + 255) / 256;
    // layer 0
    score_kernel  <<<scoreB, 256>>>(yh0, 0, 0, lam);
    spmm_kernel<0><<<ROWB, 256>>>(yh0, 0, nullptr, nullptr, nullptr);
    // layer 1
    score_kernel  <<<scoreB, 256>>>(yh1, NE, NN, lam + 1);
    spmm_kernel<1><<<ROWB, 256>>>(yh1, NN, ue, ie, out);
}

// round 7
// speedup vs baseline: 1.1505x; 1.1033x over previous
#include <cuda_runtime.h>
#include <cuda_fp16.h>

// Problem constants (fixed shapes)
#define NU 100000
#define NI 50000
#define NN 150000        // NU + NI
#define D  64
#define DE 16
#define NE 1500000
#define NP 14
#define EPS 1e-5f

#define NN2 (2 * NN)     // row counters for both layers
#define NE2 (2 * NE)     // CSR slots for both layers
#define SCAN_BLK 1024
#define NB2 ((NN2 + SCAN_BLK - 1) / SCAN_BLK)  // 293
#define ROWB ((NN + 7) / 8)                     // 18750 (8 warps/block)
#define HISTB ((NE2 / 4 + 255) / 256)           // 2930

// -------- scratch (device globals; no allocation allowed) --------
__device__ __half g_yh0[NN * D];    // LN features layer 0 (fp16)
__device__ __half g_yh1[NN * D];    // LN features layer 1 (fp16)
__device__ __half g_eh [NN * DE];   // eigs fp16
__device__ float  g_x0 [NN * D];    // layer-0 output (fp32 for final avg)
__device__ int    g_cnt[NN2];       // row degrees (both layers)
__device__ int    g_rs [NN2];       // CSR row starts (global over NE2)
__device__ int    g_cur[NN2];       // scatter cursors
__device__ int4   g_csr[NE2];       // CSR: (col, e0 bits, e1 bits, unused)
__device__ int    g_part[512];      // scan partials
__device__ int    g_scan_ctr;

// ---------------------------------------------------------------
// K0: zero counters, reset scan counter, eigs -> fp16.
// ---------------------------------------------------------------
__global__ void prep_kernel(const float* __restrict__ eigs)
{
    int i = blockIdx.x * blockDim.x + threadIdx.x;
    if (i == 0) g_scan_ctr = 0;
    if (i < NN2) g_cnt[i] = 0;
    if (i < NN * DE / 2) {
        float2 v = ((const float2*)eigs)[i];
        ((__half2*)g_eh)[i] = __floats2half2_rn(v.x, v.y);
    }
}

// ---------------------------------------------------------------
// K1: fused LN(layer 0) + histogram(both layers).
// g_cnt pre-zeroed in K0 (no in-kernel zeroing — R3's race).
// ---------------------------------------------------------------
__global__ void ln_hist_kernel(const float* __restrict__ ue,
                               const float* __restrict__ ie,
                               const int*   __restrict__ idx)
{
    if (blockIdx.x < ROWB) {
        int row = blockIdx.x * 8 + (threadIdx.x >> 5);
        if (row >= NN) return;
        int lane = threadIdx.x & 31;

        const float* p = (row < NU) ? (ue + (size_t)row * D)
                                    : (ie + (size_t)(row - NU) * D);
        float2 v = ((const float2*)p)[lane];

        float s = v.x + v.y;
        #pragma unroll
        for (int o = 16; o; o >>= 1) s += __shfl_xor_sync(0xffffffffu, s, o);
        float mu = s * (1.0f / D);

        float dx = v.x - mu, dy = v.y - mu;
        float vs = dx * dx + dy * dy;
        #pragma unroll
        for (int o = 16; o; o >>= 1) vs += __shfl_xor_sync(0xffffffffu, vs, o);
        float inv = rsqrtf(vs * (1.0f / D) + EPS);

        ((__half2*)(g_yh0 + (size_t)row * D))[lane] =
            __floats2half2_rn(dx * inv, dy * inv);
    } else {
        int e4 = (blockIdx.x - ROWB) * blockDim.x + threadIdx.x;
        if (e4 < NE2 / 4) {
            int layer = (e4 >= NE / 4);
            const int* rows = idx + (size_t)layer * 2 * NE;
            int4 r4 = ((const int4*)rows)[e4 - layer * (NE / 4)];
            int base = layer * NN;
            atomicAdd(&g_cnt[base + r4.x], 1);
            atomicAdd(&g_cnt[base + r4.y], 1);
            atomicAdd(&g_cnt[base + r4.z], 1);
            atomicAdd(&g_cnt[base + r4.w], 1);
        }
    }
}

// ---------------------------------------------------------------
// K2/K3: exclusive scan of g_cnt[NN2] -> g_rs, g_cur.
// ---------------------------------------------------------------
__device__ __forceinline__ int warp_incl_scan(int x, int lane)
{
    #pragma unroll
    for (int o = 1; o < 32; o <<= 1) {
        int t = __shfl_up_sync(0xffffffffu, x, o);
        if (lane >= o) x += t;
    }
    return x;
}

__global__ void scan_kernel()
{
    __shared__ int warpsum[32];
    __shared__ int s_total;
    __shared__ int s_isLast;

    int lane = threadIdx.x & 31;
    int wid  = threadIdx.x >> 5;
    int i = blockIdx.x * SCAN_BLK + threadIdx.x;
    int v = (i < NN2) ? g_cnt[i] : 0;

    int inc = warp_incl_scan(v, lane);
    if (lane == 31) warpsum[wid] = inc;
    __syncthreads();
    if (wid == 0) {
        int s  = warpsum[lane];
        int si = warp_incl_scan(s, lane);
        warpsum[lane] = si - s;
        if (lane == 31) s_total = si;
    }
    __syncthreads();
    int excl = inc - v + warpsum[wid];
    if (i < NN2) g_rs[i] = excl;

    if (threadIdx.x == 0) {
        g_part[blockIdx.x] = s_total;
        __threadfence();
        s_isLast = (atomicAdd(&g_scan_ctr, 1) == (int)gridDim.x - 1);
    }
    __syncthreads();

    if (s_isLast) {
        int pv = (threadIdx.x < NB2) ? g_part[threadIdx.x] : 0;
        int inc2 = warp_incl_scan(pv, lane);
        __syncthreads();
        if (lane == 31) warpsum[wid] = inc2;
        __syncthreads();
        if (wid == 0) {
            int s  = warpsum[lane];
            int si = warp_incl_scan(s, lane);
            warpsum[lane] = si - s;
        }
        __syncthreads();
        int excl2 = inc2 - pv + warpsum[wid];
        if (threadIdx.x < NB2) g_part[threadIdx.x] = excl2;
    }
}

__global__ void scan3_kernel()
{
    int i = blockIdx.x * blockDim.x + threadIdx.x;
    if (i >= NN2) return;
    int v = g_rs[i] + g_part[i >> 10];
    g_rs[i]  = v;
    g_cur[i] = v;
}

// ---------------------------------------------------------------
// K4: scores in EDGE order (4 lanes/edge) + fused CSR scatter.
// No row-sum atomics (sums computed in spmm via linearity).
// ---------------------------------------------------------------
__device__ __forceinline__ float dot8h(uint4 a, uint4 b)
{
    const __half2* ah = (const __half2*)&a;
    const __half2* bh = (const __half2*)&b;
    float d = 0.f;
    #pragma unroll
    for (int j = 0; j < 4; j++) {
        float2 af = __half22float2(ah[j]);
        float2 bf = __half22float2(bh[j]);
        d += af.x * bf.x + af.y * bf.y;
    }
    return d;
}

__global__ void score_kernel(const __half* __restrict__ yh,
                             const int*   __restrict__ rows,
                             const int*   __restrict__ cols,
                             const int*   __restrict__ pt,
                             const float* __restrict__ lam,
                             const float* __restrict__ pw,
                             int rowBase)
{
    int t = blockIdx.x * blockDim.x + threadIdx.x;
    int e = t >> 2;
    if (e >= NE) return;
    int q = t & 3;

    int r = __ldg(rows + e);
    int c = __ldg(cols + e);

    const uint4* ar = (const uint4*)(yh + (size_t)r * D);
    const uint4* bc = (const uint4*)(yh + (size_t)c * D);
    float dp = dot8h(__ldg(ar + q), __ldg(bc + q))
             + dot8h(__ldg(ar + q + 4), __ldg(bc + q + 4));

    // eigs fp16: 16 halves/node; lane q covers dims [4q, 4q+4)
    uint2 eu = __ldg((const uint2*)(g_eh + (size_t)r * DE) + q);
    uint2 ev = __ldg((const uint2*)(g_eh + (size_t)c * DE) + q);
    float2 e0f = __half22float2(*(__half2*)&eu.x);
    float2 e1f = __half22float2(*(__half2*)&eu.y);
    float2 f0f = __half22float2(*(__half2*)&ev.x);
    float2 f1f = __half22float2(*(__half2*)&ev.y);
    float ys = e0f.x * f0f.x + e0f.y * f0f.y + e1f.x * f1f.x + e1f.y * f1f.y;

    float elam = __expf(__ldg(lam));
    float p = dp * 0.125f + elam * ys;
    p += __shfl_xor_sync(0xffffffffu, p, 1);
    p += __shfl_xor_sync(0xffffffffu, p, 2);

    if (q == 0) {
        float v0 = fminf(__expf(p), 5.0f);                         // clip(exp,-5,5)
        float v1 = fminf(__expf(__ldg(pw + __ldg(pt + e))), 5.0f);
        int pos = atomicAdd(&g_cur[rowBase + r], 1);
        g_csr[pos] = make_int4(c, __float_as_int(v0), __float_as_int(v1), 0);
    }
}

// ---------------------------------------------------------------
// K5: SpMM warp/row. Accumulates both unnormalized branches AND the
// row sums in one loop (linearity of the softmax-weighted sum),
// normalizes at the end. 2-wide unroll for MLP.
//   MODE 0: epilogue LN -> yh1 fp16 + x0 fp32.
//   MODE 1: epilogue out = (emb + x0 + x)/3.
// ---------------------------------------------------------------
template<int MODE>
__global__ void spmm_kernel(const __half* __restrict__ yh,
                            int rowBase,
                            const float* __restrict__ ue,
                            const float* __restrict__ ie,
                            float* __restrict__ out)
{
    int row = blockIdx.x * 8 + (threadIdx.x >> 5);
    if (row >= NN) return;
    int lane = threadIdx.x & 31;

    int n  = g_cnt[rowBase + row];
    int st = g_rs [rowBase + row];

    float s0 = 0.f, s1 = 0.f;
    float a0x = 0.f, a0y = 0.f, a1x = 0.f, a1y = 0.f;

    int i = 0;
    for (; i + 2 <= n; i += 2) {
        int4 cwA = __ldg(&g_csr[st + i]);
        int4 cwB = __ldg(&g_csr[st + i + 1]);
        __half2 hA = ((const __half2*)(yh + (size_t)cwA.x * D))[lane];
        __half2 hB = ((const __half2*)(yh + (size_t)cwB.x * D))[lane];
        float e0A = __int_as_float(cwA.y), e1A = __int_as_float(cwA.z);
        float e0B = __int_as_float(cwB.y), e1B = __int_as_float(cwB.z);
        float2 vA = __half22float2(hA);
        float2 vB = __half22float2(hB);
        a0x += e0A * vA.x + e0B * vB.x;
        a0y += e0A * vA.y + e0B * vB.y;
        a1x += e1A * vA.x + e1B * vB.x;
        a1y += e1A * vA.y + e1B * vB.y;
        s0 += e0A + e0B;
        s1 += e1A + e1B;
    }
    if (i < n) {
        int4 cw = __ldg(&g_csr[st + i]);
        __half2 h = ((const __half2*)(yh + (size_t)cw.x * D))[lane];
        float e0 = __int_as_float(cw.y), e1 = __int_as_float(cw.z);
        float2 v = __half22float2(h);
        a0x += e0 * v.x; a0y += e0 * v.y;
        a1x += e1 * v.x; a1y += e1 * v.y;
        s0 += e0; s1 += e1;
    }

    float i0 = 0.5f / ((s0 == 0.f) ? 1.f : s0);
    float i1 = 0.5f / ((s1 == 0.f) ? 1.f : s1);
    float ax = a0x * i0 + a1x * i1;
    float ay = a0y * i0 + a1y * i1;

    if (MODE == 0) {
        // fused LayerNorm -> yh1 (fp16), plus x0 (fp32)
        float s = ax + ay;
        #pragma unroll
        for (int o = 16; o; o >>= 1) s += __shfl_xor_sync(0xffffffffu, s, o);
        float mu = s * (1.0f / D);
        float dx = ax - mu, dy = ay - mu;
        float vs = dx * dx + dy * dy;
        #pragma unroll
        for (int o = 16; o; o >>= 1) vs += __shfl_xor_sync(0xffffffffu, vs, o);
        float inv = rsqrtf(vs * (1.0f / D) + EPS);

        ((float2*)(g_x0 + (size_t)row * D))[lane] = make_float2(ax, ay);
        ((__half2*)(g_yh1 + (size_t)row * D))[lane] =
            __floats2half2_rn(dx * inv, dy * inv);
    } else {
        const float* emb = (row < NU) ? (ue + (size_t)row * D)
                                      : (ie + (size_t)(row - NU) * D);
        float2 e = ((const float2*)emb)[lane];
        float2 x = ((const float2*)(g_x0 + (size_t)row * D))[lane];
        const float t = 1.0f / 3.0f;
        ((float2*)(out + (size_t)row * D))[lane] =
            make_float2((e.x + x.x + ax) * t, (e.y + x.y + ay) * t);
    }
}

extern "C" void kernel_launch(void* const* d_in, const int* in_sizes, int n_in,
                              void* d_out, int out_size)
{
    const float* ue   = (const float*)d_in[0];  // [NU, D]
    const float* ie   = (const float*)d_in[1];  // [NI, D]
    const float* eigs = (const float*)d_in[2];  // [NN, DE]
    const float* lam  = (const float*)d_in[3];  // [2]
    const float* pw   = (const float*)d_in[4];  // [2, NP]
    const int*   idx  = (const int*)  d_in[5];  // [2, 2, NE]
    const int*   pt   = (const int*)  d_in[6];  // [2, NE]
    float* out = (float*)d_out;

    __half* yh0 = nullptr; __half* yh1 = nullptr;
    cudaGetSymbolAddress((void**)&yh0, g_yh0);
    cudaGetSymbolAddress((void**)&yh1, g_yh1);

    int prepT = NN * DE / 2;                     // 1.2M threads (covers NN2)
    prep_kernel   <<<(prepT + 255) / 256, 256>>>(eigs);
    ln_hist_kernel<<<ROWB + HISTB, 256>>>(ue, ie, idx);
    scan_kernel   <<<NB2, SCAN_BLK>>>();
    scan3_kernel  <<<(NN2 + 255) / 256, 256>>>();

    int scoreB = (NE * 4 + 255) / 256;
    // layer 0
    score_kernel  <<<scoreB, 256>>>(yh0, idx, idx + NE, pt, lam, pw, 0);
    spmm_kernel<0><<<ROWB, 256>>>(yh0, 0, nullptr, nullptr, nullptr);
    // layer 1
    score_kernel  <<<scoreB, 256>>>(yh1, idx + 2 * NE, idx + 3 * NE,
                                    pt + NE, lam + 1, pw + NP, NN);
    spmm_kernel<1><<<ROWB, 256>>>(yh1, NN, ue, ie, out);
}